// round 1
// baseline (speedup 1.0000x reference)
#include <cuda_runtime.h>
#include <math.h>
#include <stdint.h>

// Problem dims
#define VV 32000
#define HH 512
#define LL 256
#define BB 16
#define TEE 512
#define TDD 256

// Output layout: [logits (B*TD*V)][dec_max_len (1)][mu (B*L)][sigma (B*L)]
#define OFF_ML  ((size_t)BB * TDD * VV)
#define OFF_MU  (OFF_ML + 1)
#define OFF_SG  (OFF_MU + (size_t)BB * LL)

// ---------------------------------------------------------------------------
// Scratch (static device globals; no allocation allowed)
// ---------------------------------------------------------------------------
__device__ float g_gx_enc[(size_t)BB * TEE * 3 * HH];   // 50.3 MB
__device__ float g_enc_out[(size_t)BB * TEE * HH];      // 16.8 MB
__device__ float g_gx_dec[(size_t)BB * TDD * 3 * LL];   // 12.6 MB
__device__ float g_dec_out[(size_t)BB * TDD * LL];      //  4.2 MB
__device__ float g_hA[BB * HH];
__device__ float g_hB[BB * HH];
__device__ float g_sfw[BB * TEE];
__device__ float g_sbw[BB * TEE];
__device__ float g_henc[BB * 2 * HH];
__device__ float g_z[BB * LL];
__device__ unsigned g_bar_count;
__device__ volatile unsigned g_bar_gen;

// ---------------------------------------------------------------------------
// Grid-wide barrier (all CTAs co-resident: grid <= 128 <= 148 SMs)
// ---------------------------------------------------------------------------
__device__ __forceinline__ void grid_barrier(unsigned nb) {
    __threadfence();          // every thread makes its stores visible (release)
    __syncthreads();
    if (threadIdx.x == 0) {
        unsigned gen = g_bar_gen;
        unsigned arrived = atomicAdd(&g_bar_count, 1u);
        if (arrived == nb - 1) {
            g_bar_count = 0;
            __threadfence();
            g_bar_gen = gen + 1;
        } else {
            while (g_bar_gen == gen) { }
        }
        __threadfence();      // acquire
    }
    __syncthreads();
}

__device__ __forceinline__ float sigmoidf_(float x) { return 1.0f / (1.0f + expf(-x)); }

// ---------------------------------------------------------------------------
// Persistent GRU. Grid = K/CW blocks (128). Block owns CW hidden columns.
// h double-buffered in GMEM (hA/hB), accessed L2-coherently (.cg).
// ---------------------------------------------------------------------------
template<int K, int CW>
__global__ __launch_bounds__(256, 1) void gru_persist(
    const float* __restrict__ gx,    // [B, T, 3K]  (= x@Wih^T + bih, precomputed)
    const float* __restrict__ Whh,   // [3K, K]
    const float* __restrict__ bhh,   // [3K]
    const int*   __restrict__ lens,  // [B]
    const float* __restrict__ h0,    // [B, K] or nullptr (=> zeros)
    float* hA, float* hB,
    float* __restrict__ out,         // [B, T, K]
    int T)
{
    constexpr int PW = K + 4;            // smem pitch (floats), conflict-free
    constexpr int NC = 16 * 3 * CW;      // dot-product threads
    __shared__ float hs[16 * PW];
    __shared__ float ex[NC];
    __shared__ int   lens_s[16];

    const int tid = threadIdx.x;
    const int bx  = blockIdx.x;
    const unsigned NB = gridDim.x;

    if (tid < 16) lens_s[tid] = lens[tid];
    if (tid < 16 * CW) {                 // init h buffer A (this block's columns)
        int b = tid & 15, cl = tid >> 4;
        int c = bx * CW + cl;
        float v = h0 ? h0[b * K + c] : 0.0f;
        __stcg(&hA[b * K + c], v);
    }
    grid_barrier(NB);

    for (int t = 0; t < T; t++) {
        float* hcur  = (t & 1) ? hB : hA;
        float* hnext = (t & 1) ? hA : hB;

        // stage full h[B,K] into smem (coalesced .cg loads, conflict-free stores)
        const float4* hc4 = (const float4*)hcur;
        #pragma unroll
        for (int i = tid; i < 16 * K / 4; i += 256) {
            float4 v = __ldcg(hc4 + i);
            int b = i / (K / 4), kq = i % (K / 4);
            *(float4*)&hs[b * PW + 4 * kq] = v;
        }
        __syncthreads();

        if (tid < NC) {                  // gh[b, g*K+c] = h[b,:] . Whh[g*K+c,:]
            int b = tid & 15, idx = tid >> 4;
            int g = idx / CW, cl = idx % CW;
            int c = bx * CW + cl;
            const float4* w4 = (const float4*)(Whh + (size_t)(g * K + c) * K);
            const float4* h4 = (const float4*)&hs[b * PW];
            float acc = 0.0f;
            #pragma unroll 4
            for (int kq = 0; kq < K / 4; kq++) {
                float4 w = __ldg(w4 + kq);
                float4 h = h4[kq];
                acc += w.x * h.x + w.y * h.y + w.z * h.z + w.w * h.w;
            }
            ex[idx * 16 + b] = acc;
        }
        __syncthreads();

        if (tid < 16 * CW) {             // combine gates, update h, write out
            int b = tid & 15, cl = tid >> 4;
            int c = bx * CW + cl;
            const float* gxp = gx + (size_t)(b * T + t) * (3 * K);
            float ghr = ex[(0 * CW + cl) * 16 + b] + bhh[c];
            float ghz = ex[(1 * CW + cl) * 16 + b] + bhh[K + c];
            float ghn = ex[(2 * CW + cl) * 16 + b] + bhh[2 * K + c];
            float r = sigmoidf_(gxp[c]         + ghr);
            float z = sigmoidf_(gxp[K + c]     + ghz);
            float n = tanhf   (gxp[2 * K + c]  + r * ghn);
            float hold = hs[b * PW + c];
            float hnew = (1.0f - z) * n + z * hold;
            bool valid = (t < lens_s[b]);
            __stcg(&hnext[b * K + c], valid ? hnew : hold);
            out[(size_t)(b * T + t) * K + c] = valid ? hnew : 0.0f;
        }
        grid_barrier(NB);
    }
}

// ---------------------------------------------------------------------------
// 128x128x8 fp32 SGEMM-NT: C[i,j] = sum_k A[i,k]*W[j,k] + bias[j]
// Optional row gather (A row i = Atab + ids[i]*KD) and zero-row skip.
// Requires M%128==0, N%128==0, KD%8==0 (all shapes here satisfy this).
// ---------------------------------------------------------------------------
template<int KD>
__global__ __launch_bounds__(256, 2) void gemm_nt128(
    float* __restrict__ C,
    const float* __restrict__ Adirect,
    const int*   __restrict__ ids,
    const float* __restrict__ Atab,
    const float* __restrict__ W,
    const float* __restrict__ bias,
    int N,
    const int* __restrict__ skiplen,   // optional: row i -> b=i/tper, t=i%tper
    int tper)
{
    __shared__ float As[8][128];
    __shared__ float Bs[8][128];
    const int tid  = threadIdx.x;
    const int row0 = blockIdx.y * 128, col0 = blockIdx.x * 128;
    const int ty = tid >> 4, tx = tid & 15;

    if (skiplen) {   // whole M-tile is zero rows -> output = bias only
        int bb = row0 / tper, t0 = row0 % tper;
        if (t0 >= __ldg(&skiplen[bb])) {
            float4 blo = *(const float4*)(bias + col0 + tx * 8);
            float4 bhi = *(const float4*)(bias + col0 + tx * 8 + 4);
            #pragma unroll
            for (int i = 0; i < 8; i++) {
                float* cp = C + (size_t)(row0 + ty * 8 + i) * N + col0 + tx * 8;
                *(float4*)cp = blo; *(float4*)(cp + 4) = bhi;
            }
            return;
        }
    }

    const int lr  = tid >> 1;
    const int lk4 = (tid & 1) * 4;
    const float* arow = ids ? (Atab + (size_t)__ldg(&ids[row0 + lr]) * KD)
                            : (Adirect + (size_t)(row0 + lr) * KD);
    const float* wrow = W + (size_t)(col0 + lr) * KD;

    float acc[8][8];
    #pragma unroll
    for (int i = 0; i < 8; i++)
        #pragma unroll
        for (int j = 0; j < 8; j++) acc[i][j] = 0.0f;

    for (int kt = 0; kt < KD; kt += 8) {
        float4 av = *(const float4*)(arow + kt + lk4);
        float4 wv = *(const float4*)(wrow + kt + lk4);
        __syncthreads();
        As[lk4 + 0][lr] = av.x; As[lk4 + 1][lr] = av.y;
        As[lk4 + 2][lr] = av.z; As[lk4 + 3][lr] = av.w;
        Bs[lk4 + 0][lr] = wv.x; Bs[lk4 + 1][lr] = wv.y;
        Bs[lk4 + 2][lr] = wv.z; Bs[lk4 + 3][lr] = wv.w;
        __syncthreads();
        #pragma unroll
        for (int k = 0; k < 8; k++) {
            float a[8], b[8];
            *(float4*)&a[0] = *(const float4*)&As[k][ty * 8];
            *(float4*)&a[4] = *(const float4*)&As[k][ty * 8 + 4];
            *(float4*)&b[0] = *(const float4*)&Bs[k][tx * 8];
            *(float4*)&b[4] = *(const float4*)&Bs[k][tx * 8 + 4];
            #pragma unroll
            for (int i = 0; i < 8; i++)
                #pragma unroll
                for (int j = 0; j < 8; j++)
                    acc[i][j] += a[i] * b[j];
        }
    }

    float4 blo = *(const float4*)(bias + col0 + tx * 8);
    float4 bhi = *(const float4*)(bias + col0 + tx * 8 + 4);
    #pragma unroll
    for (int i = 0; i < 8; i++) {
        float* cp = C + (size_t)(row0 + ty * 8 + i) * N + col0 + tx * 8;
        float4 v0 = make_float4(acc[i][0] + blo.x, acc[i][1] + blo.y,
                                acc[i][2] + blo.z, acc[i][3] + blo.w);
        float4 v1 = make_float4(acc[i][4] + bhi.x, acc[i][5] + bhi.y,
                                acc[i][6] + bhi.z, acc[i][7] + bhi.w);
        *(float4*)cp = v0; *(float4*)(cp + 4) = v1;
    }
}

// ---------------------------------------------------------------------------
// Attention scores: sfw[b,t] = out[b,t,:].last[b,:]; sbw with first = out[b,0,:]
// ---------------------------------------------------------------------------
__global__ __launch_bounds__(256) void attn_scores() {
    const int b = blockIdx.x, tid = threadIdx.x;
    __shared__ float last_s[HH], first_s[HH];
    for (int i = tid; i < HH; i += 256) {
        last_s[i]  = g_hA[b * HH + i];
        first_s[i] = g_enc_out[((size_t)b * TEE + 0) * HH + i];
    }
    __syncthreads();
    const int w = tid >> 5, lane = tid & 31;
    for (int t = w; t < TEE; t += 8) {
        const float* orow = g_enc_out + ((size_t)(b * TEE + t)) * HH;
        float af = 0.0f, ab = 0.0f;
        #pragma unroll 4
        for (int i = lane; i < HH; i += 32) {
            float v = orow[i];
            af += v * last_s[i];
            ab += v * first_s[i];
        }
        #pragma unroll
        for (int o = 16; o > 0; o >>= 1) {
            af += __shfl_xor_sync(0xffffffffu, af, o);
            ab += __shfl_xor_sync(0xffffffffu, ab, o);
        }
        if (lane == 0) { g_sfw[b * TEE + t] = af; g_sbw[b * TEE + t] = ab; }
    }
}

__device__ __forceinline__ float blk_reduce(float v, float* red, bool ismax) {
    #pragma unroll
    for (int o = 16; o > 0; o >>= 1) {
        float u = __shfl_xor_sync(0xffffffffu, v, o);
        v = ismax ? fmaxf(v, u) : (v + u);
    }
    int w = threadIdx.x >> 5;
    if ((threadIdx.x & 31) == 0) red[w] = v;
    __syncthreads();
    if (threadIdx.x == 0) {
        float a = red[0];
        for (int i = 1; i < 8; i++) a = ismax ? fmaxf(a, red[i]) : (a + red[i]);
        red[0] = a;
    }
    __syncthreads();
    float r = red[0];
    __syncthreads();
    return r;
}

// ---------------------------------------------------------------------------
// Masked dual softmax + semantic pooling + h_enc assembly. One block per b.
// ---------------------------------------------------------------------------
__global__ __launch_bounds__(256) void softmax_semantic(const int* __restrict__ enc_len) {
    const int b = blockIdx.x, tid = threadIdx.x;
    const int len = enc_len[b];
    __shared__ float sa[TEE];
    __shared__ float red[8];

    // forward pass
    float v0 = (tid       < len) ? g_sfw[b * TEE + tid]       : -1e30f;
    float v1 = (tid + 256 < len) ? g_sfw[b * TEE + tid + 256] : -1e30f;
    float M = blk_reduce(fmaxf(v0, v1), red, true);
    float e0 = (tid       < len) ? expf(v0 - M) : 0.0f;
    float e1 = (tid + 256 < len) ? expf(v1 - M) : 0.0f;
    float S = blk_reduce(e0 + e1, red, false);
    float inv = 0.5f / S;
    sa[tid] = e0 * inv; sa[tid + 256] = e1 * inv;
    __syncthreads();

    // backward pass
    v0 = (tid       < len) ? g_sbw[b * TEE + tid]       : -1e30f;
    v1 = (tid + 256 < len) ? g_sbw[b * TEE + tid + 256] : -1e30f;
    M = blk_reduce(fmaxf(v0, v1), red, true);
    e0 = (tid       < len) ? expf(v0 - M) : 0.0f;
    e1 = (tid + 256 < len) ? expf(v1 - M) : 0.0f;
    S = blk_reduce(e0 + e1, red, false);
    inv = 0.5f / S;
    sa[tid] += e0 * inv; sa[tid + 256] += e1 * inv;
    __syncthreads();

    // semantic[b,d] = sum_t alpha[t] * out[b,t,d];  h_enc = [last, semantic]
    for (int d = tid; d < HH; d += 256) {
        float acc = 0.0f;
        #pragma unroll 4
        for (int t = 0; t < TEE; t++)
            acc += sa[t] * g_enc_out[((size_t)(b * TEE + t)) * HH + d];
        g_henc[b * 2 * HH + HH + d] = acc;
        g_henc[b * 2 * HH + d] = g_hA[b * HH + d];
    }
}

// ---------------------------------------------------------------------------
// Latent head: mu/sigma/z + tail outputs (dec_max_len, mu, sigma). 1 block/b.
// ---------------------------------------------------------------------------
__global__ __launch_bounds__(256) void latent_head(
    const float* __restrict__ W_mu, const float* __restrict__ b_mu,
    const float* __restrict__ W_ls, const float* __restrict__ b_ls,
    const float* __restrict__ noise, const int* __restrict__ dec_len,
    float* __restrict__ outbuf)
{
    const int b = blockIdx.x, tid = threadIdx.x;
    __shared__ float he[2 * HH];
    __shared__ float muv[LL], lsv[LL];
    for (int i = tid; i < 2 * HH; i += 256) he[i] = g_henc[b * 2 * HH + i];
    __syncthreads();

    const int w = tid >> 5, lane = tid & 31;
    for (int o = w; o < 2 * LL; o += 8) {
        const float* Wr; float bia; int j;
        if (o < LL) { j = o;      Wr = W_mu + (size_t)j * (2 * HH); bia = b_mu[j]; }
        else        { j = o - LL; Wr = W_ls + (size_t)j * (2 * HH); bia = b_ls[j]; }
        float acc = 0.0f;
        #pragma unroll 4
        for (int k = lane; k < 2 * HH; k += 32) acc += Wr[k] * he[k];
        #pragma unroll
        for (int s = 16; s > 0; s >>= 1) acc += __shfl_xor_sync(0xffffffffu, acc, s);
        if (lane == 0) { if (o < LL) muv[j] = acc + bia; else lsv[j] = acc + bia; }
    }
    __syncthreads();

    if (tid < LL) {
        float mu = muv[tid];
        float sg = expf(lsv[tid]);
        float zz = mu + sg * noise[b * LL + tid];
        g_z[b * LL + tid] = zz;
        outbuf[OFF_MU + b * LL + tid] = mu;
        outbuf[OFF_SG + b * LL + tid] = sg;
    }
    if (b == 0 && tid == 0) {
        int m = 0;
        for (int i = 0; i < BB; i++) m = max(m, dec_len[i]);
        outbuf[OFF_ML] = (float)m;
    }
}

// ---------------------------------------------------------------------------
// Launch
// ---------------------------------------------------------------------------
extern "C" void kernel_launch(void* const* d_in, const int* in_sizes, int n_in,
                              void* d_out, int out_size) {
    const float* emb     = (const float*)d_in[0];
    const float* enc_Wih = (const float*)d_in[1];
    const float* enc_Whh = (const float*)d_in[2];
    const float* enc_bih = (const float*)d_in[3];
    const float* enc_bhh = (const float*)d_in[4];
    const float* dec_Wih = (const float*)d_in[5];
    const float* dec_Whh = (const float*)d_in[6];
    const float* dec_bih = (const float*)d_in[7];
    const float* dec_bhh = (const float*)d_in[8];
    const float* W_mu    = (const float*)d_in[9];
    const float* b_mu    = (const float*)d_in[10];
    const float* W_ls    = (const float*)d_in[11];
    const float* b_ls    = (const float*)d_in[12];
    const float* W_fc    = (const float*)d_in[13];
    const float* b_fc    = (const float*)d_in[14];
    const float* noise   = (const float*)d_in[15];
    const int*   enc_ids = (const int*)d_in[16];
    const int*   enc_len = (const int*)d_in[17];
    const int*   dec_ids = (const int*)d_in[18];
    const int*   dec_len = (const int*)d_in[19];
    float* outbuf = (float*)d_out;

    float *p_gx_enc, *p_enc_out, *p_gx_dec, *p_dec_out, *p_hA, *p_hB;
    cudaGetSymbolAddress((void**)&p_gx_enc, g_gx_enc);
    cudaGetSymbolAddress((void**)&p_enc_out, g_enc_out);
    cudaGetSymbolAddress((void**)&p_gx_dec, g_gx_dec);
    cudaGetSymbolAddress((void**)&p_dec_out, g_dec_out);
    cudaGetSymbolAddress((void**)&p_hA, g_hA);
    cudaGetSymbolAddress((void**)&p_hB, g_hB);

    // 1) gx_enc = emb[enc_ids] @ enc_Wih^T + bih   [8192 x 1536, K=512]
    gemm_nt128<512><<<dim3(1536 / 128, (BB * TEE) / 128), 256>>>(
        p_gx_enc, nullptr, enc_ids, emb, enc_Wih, enc_bih, 3 * HH, nullptr, 1);

    // 2) encoder GRU (persistent, 512 steps)
    gru_persist<HH, 4><<<HH / 4, 256>>>(
        p_gx_enc, enc_Whh, enc_bhh, enc_len, nullptr, p_hA, p_hB, p_enc_out, TEE);

    // 3) attention scores, softmax+semantic, latent head
    attn_scores<<<BB, 256>>>();
    softmax_semantic<<<BB, 256>>>(enc_len);
    latent_head<<<BB, 256>>>(W_mu, b_mu, W_ls, b_ls, noise, dec_len, outbuf);

    // 4) gx_dec = emb[dec_ids] @ dec_Wih^T + bih   [4096 x 768, K=512]
    gemm_nt128<512><<<dim3((3 * LL) / 128, (BB * TDD) / 128), 256>>>(
        p_gx_dec, nullptr, dec_ids, emb, dec_Wih, dec_bih, 3 * LL, nullptr, 1);

    // 5) decoder GRU (persistent, 256 steps), h0 = z
    {
        float* p_z;
        cudaGetSymbolAddress((void**)&p_z, g_z);
        gru_persist<LL, 2><<<LL / 2, 256>>>(
            p_gx_dec, dec_Whh, dec_bhh, dec_len, p_z, p_hA, p_hB, p_dec_out, TDD);
    }

    // 6) logits = dec_out @ W_fc^T + b_fc  [4096 x 32000, K=256], zero-row skip
    gemm_nt128<256><<<dim3(VV / 128, (BB * TDD) / 128), 256>>>(
        outbuf, p_dec_out, nullptr, nullptr, W_fc, b_fc, VV, dec_len, TDD);
}

// round 3
// speedup vs baseline: 1.2658x; 1.2658x over previous
#include <cuda_runtime.h>
#include <math.h>
#include <stdint.h>

// Problem dims
#define VV 32000
#define HH 512
#define LL 256
#define BB 16
#define TEE 512
#define TDD 256

// Output layout: [logits (B*TD*V)][dec_max_len (1)][mu (B*L)][sigma (B*L)]
#define OFF_ML  ((size_t)BB * TDD * VV)
#define OFF_MU  (OFF_ML + 1)
#define OFF_SG  (OFF_MU + (size_t)BB * LL)

// ---------------------------------------------------------------------------
// Scratch (static device globals; no allocation allowed)
// ---------------------------------------------------------------------------
__device__ float g_gx_enc[(size_t)BB * TEE * 3 * HH];   // 50.3 MB
__device__ float g_enc_out[(size_t)BB * TEE * HH];      // 16.8 MB
__device__ float g_gx_dec[(size_t)BB * TDD * 3 * LL];   // 12.6 MB
__device__ float g_dec_out[(size_t)BB * TDD * LL];      //  4.2 MB
__device__ float g_hA[BB * HH];
__device__ float g_hB[BB * HH];
__device__ float g_sfw[BB * TEE];
__device__ float g_sbw[BB * TEE];
__device__ float g_henc[BB * 2 * HH];
__device__ float g_z[BB * LL];
__device__ unsigned g_bar_count;
__device__ volatile unsigned g_bar_gen;

// ---------------------------------------------------------------------------
// Grid-wide barrier (R1-proven version; all CTAs co-resident, grid <= 128)
// ---------------------------------------------------------------------------
__device__ __forceinline__ void grid_barrier(unsigned nb) {
    __threadfence();          // every thread makes its stores visible (release)
    __syncthreads();
    if (threadIdx.x == 0) {
        unsigned gen = g_bar_gen;
        unsigned arrived = atomicAdd(&g_bar_count, 1u);
        if (arrived == nb - 1) {
            g_bar_count = 0;
            __threadfence();
            g_bar_gen = gen + 1;
        } else {
            while (g_bar_gen == gen) { }
        }
        __threadfence();      // acquire
    }
    __syncthreads();
}

__device__ __forceinline__ float sigmoidf_(float x) { return 1.0f / (1.0f + expf(-x)); }

// ---------------------------------------------------------------------------
// Persistent GRU (R2 body under test). Grid = K/CW blocks (128).
// smem h pitch = K+2 words -> bank(b,k) = (2b + k) mod 32: the 16 b-lanes of a
// warp hit distinct banks on float2 loads; the 2 out-idx groups broadcast.
// ---------------------------------------------------------------------------
template<int K, int CW>
__global__ __launch_bounds__(256, 1) void gru_persist(
    const float* __restrict__ gx,    // [B, T, 3K]  (= x@Wih^T + bih, precomputed)
    const float* __restrict__ Whh,   // [3K, K]
    const float* __restrict__ bhh,   // [3K]
    const int*   __restrict__ lens,  // [B]
    const float* __restrict__ h0,    // [B, K] or nullptr (=> zeros)
    float* hA, float* hB,
    float* __restrict__ out,         // [B, T, K]
    int T)
{
    constexpr int PW = K + 2;            // smem pitch (floats)
    constexpr int NC = 16 * 3 * CW;      // dot-product threads (192 / 96)
    constexpr int NU = 16 * CW;          // update threads (64 / 32)
    __shared__ float hs[16 * PW];
    __shared__ float ex[NC];
    __shared__ int   lens_s[16];

    const int tid = threadIdx.x;
    const int bx  = blockIdx.x;
    const unsigned NB = gridDim.x;

    // dot-thread identity + persistent weight row pointer + bias
    const float4* wp = nullptr;
    float bhv = 0.0f;
    int db = tid & 15;
    if (tid < NC) {
        int didx = tid >> 4;             // 0..3CW-1
        int dg = didx / CW, dcl = didx % CW;
        int dc = bx * CW + dcl;
        wp = (const float4*)(Whh + (size_t)(dg * K + dc) * K);
        bhv = bhh[dg * K + dc];
    }
    // update-thread identity
    int ub = tid & 15, ucl = tid >> 4;
    int uc = bx * CW + ucl;

    if (tid < 16) lens_s[tid] = lens[tid];
    if (tid < NU) {                      // init h buffer A (this block's columns)
        float v = h0 ? h0[ub * K + uc] : 0.0f;
        __stcg(&hA[ub * K + uc], v);
    }
    grid_barrier(NB);

    for (int t = 0; t < T; t++) {
        float* hcur  = (t & 1) ? hB : hA;
        float* hnext = (t & 1) ? hA : hB;

        // prefetch gx[t] for update threads (independent of h -> hides latency)
        float gxr = 0.f, gxz = 0.f, gxn = 0.f;
        if (tid < NU) {
            const float* gxp = gx + (size_t)(ub * T + t) * (3 * K);
            gxr = __ldg(gxp + uc);
            gxz = __ldg(gxp + K + uc);
            gxn = __ldg(gxp + 2 * K + uc);
        }

        // stage full h[B,K] into smem (float2, pitch K+2)
        const float2* hc2 = (const float2*)hcur;
        #pragma unroll
        for (int i = tid; i < 16 * K / 2; i += 256) {
            float2 v = __ldcg(hc2 + i);
            int b = i / (K / 2), kh = i % (K / 2);
            *(float2*)&hs[b * PW + 2 * kh] = v;
        }
        __syncthreads();

        if (tid < NC) {                  // gh[b, g*K+c] = h[b,:] . Whh[g*K+c,:]
            const float2* hp = (const float2*)&hs[db * PW];
            float acc = 0.0f;
            #pragma unroll 8
            for (int k4 = 0; k4 < K / 4; k4++) {
                float4 w = __ldg(wp + k4);
                float2 h0v = hp[2 * k4];
                float2 h1v = hp[2 * k4 + 1];
                acc += w.x * h0v.x + w.y * h0v.y + w.z * h1v.x + w.w * h1v.y;
            }
            ex[(tid >> 4) * 16 + db] = acc + bhv;
        }
        __syncthreads();

        if (tid < NU) {                  // combine gates, update h, write out
            float ghr = ex[(0 * CW + ucl) * 16 + ub];
            float ghz = ex[(1 * CW + ucl) * 16 + ub];
            float ghn = ex[(2 * CW + ucl) * 16 + ub];
            float r = sigmoidf_(gxr + ghr);
            float z = sigmoidf_(gxz + ghz);
            float n = tanhf   (gxn + r * ghn);
            float hold = hs[ub * PW + uc];
            float hnew = (1.0f - z) * n + z * hold;
            bool valid = (t < lens_s[ub]);
            __stcg(&hnext[ub * K + uc], valid ? hnew : hold);
            out[(size_t)(ub * T + t) * K + uc] = valid ? hnew : 0.0f;
        }
        grid_barrier(NB);
    }
}

// ---------------------------------------------------------------------------
// 128x128x8 fp32 SGEMM-NT (R1-proven single-buffer version).
// C[i,j] = sum_k A[i,k]*W[j,k] + bias[j]
// Optional row gather (A row i = Atab + ids[i]*KD) and zero-row tile skip.
// ---------------------------------------------------------------------------
template<int KD>
__global__ __launch_bounds__(256, 2) void gemm_nt128(
    float* __restrict__ C,
    const float* __restrict__ Adirect,
    const int*   __restrict__ ids,
    const float* __restrict__ Atab,
    const float* __restrict__ W,
    const float* __restrict__ bias,
    int N,
    const int* __restrict__ skiplen,   // optional: row i -> b=i/tper, t=i%tper
    int tper)
{
    __shared__ float As[8][128];
    __shared__ float Bs[8][128];
    const int tid  = threadIdx.x;
    const int row0 = blockIdx.y * 128, col0 = blockIdx.x * 128;
    const int ty = tid >> 4, tx = tid & 15;

    if (skiplen) {   // whole M-tile is zero rows -> output = bias only
        int bb = row0 / tper, t0 = row0 % tper;
        if (t0 >= __ldg(&skiplen[bb])) {
            float4 blo = *(const float4*)(bias + col0 + tx * 8);
            float4 bhi = *(const float4*)(bias + col0 + tx * 8 + 4);
            #pragma unroll
            for (int i = 0; i < 8; i++) {
                float* cp = C + (size_t)(row0 + ty * 8 + i) * N + col0 + tx * 8;
                *(float4*)cp = blo; *(float4*)(cp + 4) = bhi;
            }
            return;
        }
    }

    const int lr  = tid >> 1;
    const int lk4 = (tid & 1) * 4;
    const float* arow = ids ? (Atab + (size_t)__ldg(&ids[row0 + lr]) * KD)
                            : (Adirect + (size_t)(row0 + lr) * KD);
    const float* wrow = W + (size_t)(col0 + lr) * KD;

    float acc[8][8];
    #pragma unroll
    for (int i = 0; i < 8; i++)
        #pragma unroll
        for (int j = 0; j < 8; j++) acc[i][j] = 0.0f;

    for (int kt = 0; kt < KD; kt += 8) {
        float4 av = *(const float4*)(arow + kt + lk4);
        float4 wv = *(const float4*)(wrow + kt + lk4);
        __syncthreads();
        As[lk4 + 0][lr] = av.x; As[lk4 + 1][lr] = av.y;
        As[lk4 + 2][lr] = av.z; As[lk4 + 3][lr] = av.w;
        Bs[lk4 + 0][lr] = wv.x; Bs[lk4 + 1][lr] = wv.y;
        Bs[lk4 + 2][lr] = wv.z; Bs[lk4 + 3][lr] = wv.w;
        __syncthreads();
        #pragma unroll
        for (int k = 0; k < 8; k++) {
            float a[8], b[8];
            *(float4*)&a[0] = *(const float4*)&As[k][ty * 8];
            *(float4*)&a[4] = *(const float4*)&As[k][ty * 8 + 4];
            *(float4*)&b[0] = *(const float4*)&Bs[k][tx * 8];
            *(float4*)&b[4] = *(const float4*)&Bs[k][tx * 8 + 4];
            #pragma unroll
            for (int i = 0; i < 8; i++)
                #pragma unroll
                for (int j = 0; j < 8; j++)
                    acc[i][j] += a[i] * b[j];
        }
    }

    float4 blo = *(const float4*)(bias + col0 + tx * 8);
    float4 bhi = *(const float4*)(bias + col0 + tx * 8 + 4);
    #pragma unroll
    for (int i = 0; i < 8; i++) {
        float* cp = C + (size_t)(row0 + ty * 8 + i) * N + col0 + tx * 8;
        float4 v0 = make_float4(acc[i][0] + blo.x, acc[i][1] + blo.y,
                                acc[i][2] + blo.z, acc[i][3] + blo.w);
        float4 v1 = make_float4(acc[i][4] + bhi.x, acc[i][5] + bhi.y,
                                acc[i][6] + bhi.z, acc[i][7] + bhi.w);
        *(float4*)cp = v0; *(float4*)(cp + 4) = v1;
    }
}

// ---------------------------------------------------------------------------
// Padding no-ops (try to land ncu's -s 5 -c 1 capture on gru_persist<512,4>)
// ---------------------------------------------------------------------------
__global__ void noop_a() {}
__global__ void noop_b() {}
__global__ void noop_c() {}

// ---------------------------------------------------------------------------
// Attention scores (R1-proven): sfw[b,t] = out[b,t,:].last[b,:]; sbw with first
// ---------------------------------------------------------------------------
__global__ __launch_bounds__(256) void attn_scores() {
    const int b = blockIdx.x, tid = threadIdx.x;
    __shared__ float last_s[HH], first_s[HH];
    for (int i = tid; i < HH; i += 256) {
        last_s[i]  = g_hA[b * HH + i];
        first_s[i] = g_enc_out[((size_t)b * TEE + 0) * HH + i];
    }
    __syncthreads();
    const int w = tid >> 5, lane = tid & 31;
    for (int t = w; t < TEE; t += 8) {
        const float* orow = g_enc_out + ((size_t)(b * TEE + t)) * HH;
        float af = 0.0f, ab = 0.0f;
        #pragma unroll 4
        for (int i = lane; i < HH; i += 32) {
            float v = orow[i];
            af += v * last_s[i];
            ab += v * first_s[i];
        }
        #pragma unroll
        for (int o = 16; o > 0; o >>= 1) {
            af += __shfl_xor_sync(0xffffffffu, af, o);
            ab += __shfl_xor_sync(0xffffffffu, ab, o);
        }
        if (lane == 0) { g_sfw[b * TEE + t] = af; g_sbw[b * TEE + t] = ab; }
    }
}

__device__ __forceinline__ float blk_reduce(float v, float* red, bool ismax) {
    #pragma unroll
    for (int o = 16; o > 0; o >>= 1) {
        float u = __shfl_xor_sync(0xffffffffu, v, o);
        v = ismax ? fmaxf(v, u) : (v + u);
    }
    int w = threadIdx.x >> 5;
    if ((threadIdx.x & 31) == 0) red[w] = v;
    __syncthreads();
    if (threadIdx.x == 0) {
        float a = red[0];
        for (int i = 1; i < 8; i++) a = ismax ? fmaxf(a, red[i]) : (a + red[i]);
        red[0] = a;
    }
    __syncthreads();
    float r = red[0];
    __syncthreads();
    return r;
}

// ---------------------------------------------------------------------------
// Masked dual softmax + semantic pooling + h_enc assembly (R1-proven).
// ---------------------------------------------------------------------------
__global__ __launch_bounds__(256) void softmax_semantic(const int* __restrict__ enc_len) {
    const int b = blockIdx.x, tid = threadIdx.x;
    const int len = enc_len[b];
    __shared__ float sa[TEE];
    __shared__ float red[8];

    // forward pass
    float v0 = (tid       < len) ? g_sfw[b * TEE + tid]       : -1e30f;
    float v1 = (tid + 256 < len) ? g_sfw[b * TEE + tid + 256] : -1e30f;
    float M = blk_reduce(fmaxf(v0, v1), red, true);
    float e0 = (tid       < len) ? expf(v0 - M) : 0.0f;
    float e1 = (tid + 256 < len) ? expf(v1 - M) : 0.0f;
    float S = blk_reduce(e0 + e1, red, false);
    float inv = 0.5f / S;
    sa[tid] = e0 * inv; sa[tid + 256] = e1 * inv;
    __syncthreads();

    // backward pass
    v0 = (tid       < len) ? g_sbw[b * TEE + tid]       : -1e30f;
    v1 = (tid + 256 < len) ? g_sbw[b * TEE + tid + 256] : -1e30f;
    M = blk_reduce(fmaxf(v0, v1), red, true);
    e0 = (tid       < len) ? expf(v0 - M) : 0.0f;
    e1 = (tid + 256 < len) ? expf(v1 - M) : 0.0f;
    S = blk_reduce(e0 + e1, red, false);
    inv = 0.5f / S;
    sa[tid] += e0 * inv; sa[tid + 256] += e1 * inv;
    __syncthreads();

    // semantic[b,d] = sum_t alpha[t] * out[b,t,d];  h_enc = [last, semantic]
    for (int d = tid; d < HH; d += 256) {
        float acc = 0.0f;
        #pragma unroll 4
        for (int t = 0; t < TEE; t++)
            acc += sa[t] * g_enc_out[((size_t)(b * TEE + t)) * HH + d];
        g_henc[b * 2 * HH + HH + d] = acc;
        g_henc[b * 2 * HH + d] = g_hA[b * HH + d];
    }
}

// ---------------------------------------------------------------------------
// Latent head (R1-proven): mu/sigma/z + tail outputs. 1 block per b.
// ---------------------------------------------------------------------------
__global__ __launch_bounds__(256) void latent_head(
    const float* __restrict__ W_mu, const float* __restrict__ b_mu,
    const float* __restrict__ W_ls, const float* __restrict__ b_ls,
    const float* __restrict__ noise, const int* __restrict__ dec_len,
    float* __restrict__ outbuf)
{
    const int b = blockIdx.x, tid = threadIdx.x;
    __shared__ float he[2 * HH];
    __shared__ float muv[LL], lsv[LL];
    for (int i = tid; i < 2 * HH; i += 256) he[i] = g_henc[b * 2 * HH + i];
    __syncthreads();

    const int w = tid >> 5, lane = tid & 31;
    for (int o = w; o < 2 * LL; o += 8) {
        const float* Wr; float bia; int j;
        if (o < LL) { j = o;      Wr = W_mu + (size_t)j * (2 * HH); bia = b_mu[j]; }
        else        { j = o - LL; Wr = W_ls + (size_t)j * (2 * HH); bia = b_ls[j]; }
        float acc = 0.0f;
        #pragma unroll 4
        for (int k = lane; k < 2 * HH; k += 32) acc += Wr[k] * he[k];
        #pragma unroll
        for (int s = 16; s > 0; s >>= 1) acc += __shfl_xor_sync(0xffffffffu, acc, s);
        if (lane == 0) { if (o < LL) muv[j] = acc + bia; else lsv[j] = acc + bia; }
    }
    __syncthreads();

    if (tid < LL) {
        float mu = muv[tid];
        float sg = expf(lsv[tid]);
        float zz = mu + sg * noise[b * LL + tid];
        g_z[b * LL + tid] = zz;
        outbuf[OFF_MU + b * LL + tid] = mu;
        outbuf[OFF_SG + b * LL + tid] = sg;
    }
    if (b == 0 && tid == 0) {
        int m = 0;
        for (int i = 0; i < BB; i++) m = max(m, dec_len[i]);
        outbuf[OFF_ML] = (float)m;
    }
}

// ---------------------------------------------------------------------------
// Launch (R1 order, plus no-op padding before the encoder GRU)
// ---------------------------------------------------------------------------
extern "C" void kernel_launch(void* const* d_in, const int* in_sizes, int n_in,
                              void* d_out, int out_size) {
    const float* emb     = (const float*)d_in[0];
    const float* enc_Wih = (const float*)d_in[1];
    const float* enc_Whh = (const float*)d_in[2];
    const float* enc_bih = (const float*)d_in[3];
    const float* enc_bhh = (const float*)d_in[4];
    const float* dec_Wih = (const float*)d_in[5];
    const float* dec_Whh = (const float*)d_in[6];
    const float* dec_bih = (const float*)d_in[7];
    const float* dec_bhh = (const float*)d_in[8];
    const float* W_mu    = (const float*)d_in[9];
    const float* b_mu    = (const float*)d_in[10];
    const float* W_ls    = (const float*)d_in[11];
    const float* b_ls    = (const float*)d_in[12];
    const float* W_fc    = (const float*)d_in[13];
    const float* b_fc    = (const float*)d_in[14];
    const float* noise   = (const float*)d_in[15];
    const int*   enc_ids = (const int*)d_in[16];
    const int*   enc_len = (const int*)d_in[17];
    const int*   dec_ids = (const int*)d_in[18];
    const int*   dec_len = (const int*)d_in[19];
    float* outbuf = (float*)d_out;

    float *p_gx_enc, *p_enc_out, *p_gx_dec, *p_dec_out, *p_hA, *p_hB, *p_z;
    cudaGetSymbolAddress((void**)&p_gx_enc, g_gx_enc);
    cudaGetSymbolAddress((void**)&p_enc_out, g_enc_out);
    cudaGetSymbolAddress((void**)&p_gx_dec, g_gx_dec);
    cudaGetSymbolAddress((void**)&p_dec_out, g_dec_out);
    cudaGetSymbolAddress((void**)&p_hA, g_hA);
    cudaGetSymbolAddress((void**)&p_hB, g_hB);
    cudaGetSymbolAddress((void**)&p_z, g_z);

    // 1) gx_enc = emb[enc_ids] @ enc_Wih^T + bih   [8192 x 1536, K=512]
    gemm_nt128<512><<<dim3(1536 / 128, (BB * TEE) / 128), 256>>>(
        p_gx_enc, nullptr, enc_ids, emb, enc_Wih, enc_bih, 3 * HH, nullptr, 1);

    // 2-4) padding no-ops (profiling alignment)
    noop_a<<<1, 32>>>();
    noop_b<<<1, 32>>>();
    noop_c<<<1, 32>>>();

    // 5) encoder GRU (persistent, 512 steps)  <-- hoped profiled launch
    gru_persist<HH, 4><<<HH / 4, 256>>>(
        p_gx_enc, enc_Whh, enc_bhh, enc_len, nullptr, p_hA, p_hB, p_enc_out, TEE);

    // 6-8) attention + latent path (R1 versions)
    attn_scores<<<BB, 256>>>();
    softmax_semantic<<<BB, 256>>>(enc_len);
    latent_head<<<BB, 256>>>(W_mu, b_mu, W_ls, b_ls, noise, dec_len, outbuf);

    // 9) gx_dec = emb[dec_ids] @ dec_Wih^T + bih   [4096 x 768, K=512]
    gemm_nt128<512><<<dim3((3 * LL) / 128, (BB * TDD) / 128), 256>>>(
        p_gx_dec, nullptr, dec_ids, emb, dec_Wih, dec_bih, 3 * LL, nullptr, 1);

    // 10) decoder GRU (persistent, 256 steps), h0 = z
    gru_persist<LL, 2><<<LL / 2, 256>>>(
        p_gx_dec, dec_Whh, dec_bhh, dec_len, p_z, p_hA, p_hB, p_dec_out, TDD);

    // 11) logits = dec_out @ W_fc^T + b_fc  [4096 x 32000, K=256], zero-row skip
    gemm_nt128<256><<<dim3(VV / 128, (BB * TDD) / 128), 256>>>(
        outbuf, p_dec_out, nullptr, nullptr, W_fc, b_fc, VV, dec_len, TDD);
}

// round 4
// speedup vs baseline: 1.3350x; 1.0547x over previous
#include <cuda_runtime.h>
#include <math.h>
#include <stdint.h>

// Problem dims
#define VV 32000
#define HH 512
#define LL 256
#define BB 16
#define TEE 512
#define TDD 256

// Output layout: [logits (B*TD*V)][dec_max_len (1)][mu (B*L)][sigma (B*L)]
#define OFF_ML  ((size_t)BB * TDD * VV)
#define OFF_MU  (OFF_ML + 1)
#define OFF_SG  (OFF_MU + (size_t)BB * LL)

// ---------------------------------------------------------------------------
// Scratch (static device globals; no allocation allowed)
// ---------------------------------------------------------------------------
__device__ float g_gx_enc[(size_t)BB * TEE * 3 * HH];   // 50.3 MB
__device__ float g_enc_out[(size_t)BB * TEE * HH];      // 16.8 MB
__device__ float g_gx_dec[(size_t)BB * TDD * 3 * LL];   // 12.6 MB
__device__ float g_dec_out[(size_t)BB * TDD * LL];      //  4.2 MB
__device__ float g_hA[BB * HH];
__device__ float g_hB[BB * HH];
__device__ float g_sfw[BB * TEE];
__device__ float g_sbw[BB * TEE];
__device__ float g_henc[BB * 2 * HH];
__device__ float g_z[BB * LL];
__device__ unsigned g_bar_count;
__device__ volatile unsigned g_bar_gen;

// ---------------------------------------------------------------------------
// Grid-wide barrier (R1-proven version; all CTAs co-resident, grid <= 128)
// ---------------------------------------------------------------------------
__device__ __forceinline__ void grid_barrier(unsigned nb) {
    __threadfence();          // every thread makes its stores visible (release)
    __syncthreads();
    if (threadIdx.x == 0) {
        unsigned gen = g_bar_gen;
        unsigned arrived = atomicAdd(&g_bar_count, 1u);
        if (arrived == nb - 1) {
            g_bar_count = 0;
            __threadfence();
            g_bar_gen = gen + 1;
        } else {
            while (g_bar_gen == gen) { }
        }
        __threadfence();      // acquire
    }
    __syncthreads();
}

__device__ __forceinline__ float sigmoidf_(float x) { return 1.0f / (1.0f + expf(-x)); }

// ---------------------------------------------------------------------------
// Persistent GRU. Grid = K/CW blocks (128). Block owns CW hidden columns.
// smem h pitch = K+2 words; float2 loads are bank-conflict-free across the
// 16 batch lanes. Dot phase uses 4 accumulators to break the FFMA chain.
// ---------------------------------------------------------------------------
template<int K, int CW>
__global__ __launch_bounds__(256, 1) void gru_persist(
    const float* __restrict__ gx,    // [B, T, 3K]  (= x@Wih^T + bih, precomputed)
    const float* __restrict__ Whh,   // [3K, K]
    const float* __restrict__ bhh,   // [3K]
    const int*   __restrict__ lens,  // [B]
    const float* __restrict__ h0,    // [B, K] or nullptr (=> zeros)
    float* hA, float* hB,
    float* __restrict__ out,         // [B, T, K]
    int T)
{
    constexpr int PW = K + 2;            // smem pitch (floats)
    constexpr int NC = 16 * 3 * CW;      // dot-product threads (192 / 96)
    constexpr int NU = 16 * CW;          // update threads (64 / 32)
    __shared__ float hs[16 * PW];
    __shared__ float ex[NC];
    __shared__ int   lens_s[16];

    const int tid = threadIdx.x;
    const int bx  = blockIdx.x;
    const unsigned NB = gridDim.x;

    // dot-thread identity + persistent weight row pointer + bias
    const float4* wp = nullptr;
    float bhv = 0.0f;
    int db = tid & 15;
    if (tid < NC) {
        int didx = tid >> 4;             // 0..3CW-1
        int dg = didx / CW, dcl = didx % CW;
        int dc = bx * CW + dcl;
        wp = (const float4*)(Whh + (size_t)(dg * K + dc) * K);
        bhv = bhh[dg * K + dc];
    }
    // update-thread identity
    int ub = tid & 15, ucl = tid >> 4;
    int uc = bx * CW + ucl;

    if (tid < 16) lens_s[tid] = lens[tid];
    if (tid < NU) {                      // init h buffer A (this block's columns)
        float v = h0 ? h0[ub * K + uc] : 0.0f;
        __stcg(&hA[ub * K + uc], v);
    }
    grid_barrier(NB);

    for (int t = 0; t < T; t++) {
        float* hcur  = (t & 1) ? hB : hA;
        float* hnext = (t & 1) ? hA : hB;

        // prefetch gx[t] for update threads (independent of h -> hides latency)
        float gxr = 0.f, gxz = 0.f, gxn = 0.f;
        if (tid < NU) {
            const float* gxp = gx + (size_t)(ub * T + t) * (3 * K);
            gxr = __ldg(gxp + uc);
            gxz = __ldg(gxp + K + uc);
            gxn = __ldg(gxp + 2 * K + uc);
        }

        // stage full h[B,K] into smem (float2, pitch K+2)
        const float2* hc2 = (const float2*)hcur;
        #pragma unroll
        for (int i = tid; i < 16 * K / 2; i += 256) {
            float2 v = __ldcg(hc2 + i);
            int b = i / (K / 2), kh = i % (K / 2);
            *(float2*)&hs[b * PW + 2 * kh] = v;
        }
        __syncthreads();

        if (tid < NC) {                  // gh[b, g*K+c] = h[b,:] . Whh[g*K+c,:]
            const float2* hp = (const float2*)&hs[db * PW];
            float a0 = 0.f, a1 = 0.f, a2 = 0.f, a3 = 0.f;
            #pragma unroll 4
            for (int kk = 0; kk < K / 16; kk++) {
                float4 w0 = __ldg(wp + 4 * kk + 0);
                float4 w1 = __ldg(wp + 4 * kk + 1);
                float4 w2 = __ldg(wp + 4 * kk + 2);
                float4 w3 = __ldg(wp + 4 * kk + 3);
                float2 h0v = hp[8 * kk + 0], h1v = hp[8 * kk + 1];
                float2 h2v = hp[8 * kk + 2], h3v = hp[8 * kk + 3];
                float2 h4v = hp[8 * kk + 4], h5v = hp[8 * kk + 5];
                float2 h6v = hp[8 * kk + 6], h7v = hp[8 * kk + 7];
                a0 += w0.x * h0v.x + w0.y * h0v.y + w0.z * h1v.x + w0.w * h1v.y;
                a1 += w1.x * h2v.x + w1.y * h2v.y + w1.z * h3v.x + w1.w * h3v.y;
                a2 += w2.x * h4v.x + w2.y * h4v.y + w2.z * h5v.x + w2.w * h5v.y;
                a3 += w3.x * h6v.x + w3.y * h6v.y + w3.z * h7v.x + w3.w * h7v.y;
            }
            ex[(tid >> 4) * 16 + db] = ((a0 + a1) + (a2 + a3)) + bhv;
        }
        __syncthreads();

        if (tid < NU) {                  // combine gates, update h, write out
            float ghr = ex[(0 * CW + ucl) * 16 + ub];
            float ghz = ex[(1 * CW + ucl) * 16 + ub];
            float ghn = ex[(2 * CW + ucl) * 16 + ub];
            float r = sigmoidf_(gxr + ghr);
            float z = sigmoidf_(gxz + ghz);
            float n = tanhf   (gxn + r * ghn);
            float hold = hs[ub * PW + uc];
            float hnew = (1.0f - z) * n + z * hold;
            bool valid = (t < lens_s[ub]);
            __stcg(&hnext[ub * K + uc], valid ? hnew : hold);
            out[(size_t)(ub * T + t) * K + uc] = valid ? hnew : 0.0f;
        }
        grid_barrier(NB);
    }
}

// ---------------------------------------------------------------------------
// 128x128x8 fp32 SGEMM-NT, double-buffered smem, 1 sync per k-tile.
// C[i,j] = sum_k A[i,k]*W[j,k] + bias[j]
// Optional row gather (A row i = Atab + ids[i]*KD) and zero-row tile skip.
// ---------------------------------------------------------------------------
template<int KD>
__global__ __launch_bounds__(256, 2) void gemm_nt128(
    float* __restrict__ C,
    const float* __restrict__ Adirect,
    const int*   __restrict__ ids,
    const float* __restrict__ Atab,
    const float* __restrict__ W,
    const float* __restrict__ bias,
    int N,
    const int* __restrict__ skiplen,   // optional: row i -> b=i/tper, t=i%tper
    int tper)
{
    __shared__ float As[2][8][128];
    __shared__ float Bs[2][8][128];
    const int tid  = threadIdx.x;
    const int row0 = blockIdx.y * 128, col0 = blockIdx.x * 128;
    const int ty = tid >> 4, tx = tid & 15;

    if (skiplen) {   // whole M-tile is zero rows -> output = bias only
        int bb = row0 / tper, t0 = row0 % tper;
        if (t0 >= __ldg(&skiplen[bb])) {
            float4 blo = *(const float4*)(bias + col0 + tx * 8);
            float4 bhi = *(const float4*)(bias + col0 + tx * 8 + 4);
            #pragma unroll
            for (int i = 0; i < 8; i++) {
                float* cp = C + (size_t)(row0 + ty * 8 + i) * N + col0 + tx * 8;
                *(float4*)cp = blo; *(float4*)(cp + 4) = bhi;
            }
            return;
        }
    }

    const int lr  = tid >> 1;
    const int lk4 = (tid & 1) * 4;
    const float* arow = ids ? (Atab + (size_t)__ldg(&ids[row0 + lr]) * KD)
                            : (Adirect + (size_t)(row0 + lr) * KD);
    const float* wrow = W + (size_t)(col0 + lr) * KD;

    // prologue: fill buffer 0
    {
        float4 av = *(const float4*)(arow + lk4);
        float4 wv = *(const float4*)(wrow + lk4);
        As[0][lk4 + 0][lr] = av.x; As[0][lk4 + 1][lr] = av.y;
        As[0][lk4 + 2][lr] = av.z; As[0][lk4 + 3][lr] = av.w;
        Bs[0][lk4 + 0][lr] = wv.x; Bs[0][lk4 + 1][lr] = wv.y;
        Bs[0][lk4 + 2][lr] = wv.z; Bs[0][lk4 + 3][lr] = wv.w;
    }
    __syncthreads();

    float acc[8][8];
    #pragma unroll
    for (int i = 0; i < 8; i++)
        #pragma unroll
        for (int j = 0; j < 8; j++) acc[i][j] = 0.0f;

    constexpr int NK = KD / 8;
    #pragma unroll 1
    for (int kt = 0; kt < NK; kt++) {
        const int cur = kt & 1;
        float4 av2, wv2;
        if (kt + 1 < NK) {
            av2 = *(const float4*)(arow + (kt + 1) * 8 + lk4);
            wv2 = *(const float4*)(wrow + (kt + 1) * 8 + lk4);
        }
        #pragma unroll
        for (int k = 0; k < 8; k++) {
            float a[8], b[8];
            *(float4*)&a[0] = *(const float4*)&As[cur][k][ty * 8];
            *(float4*)&a[4] = *(const float4*)&As[cur][k][ty * 8 + 4];
            *(float4*)&b[0] = *(const float4*)&Bs[cur][k][tx * 8];
            *(float4*)&b[4] = *(const float4*)&Bs[cur][k][tx * 8 + 4];
            #pragma unroll
            for (int i = 0; i < 8; i++)
                #pragma unroll
                for (int j = 0; j < 8; j++)
                    acc[i][j] += a[i] * b[j];
        }
        if (kt + 1 < NK) {
            const int nxt = cur ^ 1;
            As[nxt][lk4 + 0][lr] = av2.x; As[nxt][lk4 + 1][lr] = av2.y;
            As[nxt][lk4 + 2][lr] = av2.z; As[nxt][lk4 + 3][lr] = av2.w;
            Bs[nxt][lk4 + 0][lr] = wv2.x; Bs[nxt][lk4 + 1][lr] = wv2.y;
            Bs[nxt][lk4 + 2][lr] = wv2.z; Bs[nxt][lk4 + 3][lr] = wv2.w;
        }
        __syncthreads();
    }

    float4 blo = *(const float4*)(bias + col0 + tx * 8);
    float4 bhi = *(const float4*)(bias + col0 + tx * 8 + 4);
    #pragma unroll
    for (int i = 0; i < 8; i++) {
        float* cp = C + (size_t)(row0 + ty * 8 + i) * N + col0 + tx * 8;
        float4 v0 = make_float4(acc[i][0] + blo.x, acc[i][1] + blo.y,
                                acc[i][2] + blo.z, acc[i][3] + blo.w);
        float4 v1 = make_float4(acc[i][4] + bhi.x, acc[i][5] + bhi.y,
                                acc[i][6] + bhi.z, acc[i][7] + bhi.w);
        *(float4*)cp = v0; *(float4*)(cp + 4) = v1;
    }
}

// ---------------------------------------------------------------------------
// Padding no-ops: profiled slot = my 4th launch => 2 noops put gru_enc there
// ---------------------------------------------------------------------------
__global__ void noop_a() {}
__global__ void noop_b() {}

// ---------------------------------------------------------------------------
// Attention scores (R1-proven): sfw[b,t] = out[b,t,:].last[b,:]; sbw with first
// ---------------------------------------------------------------------------
__global__ __launch_bounds__(256) void attn_scores() {
    const int b = blockIdx.x, tid = threadIdx.x;
    __shared__ float last_s[HH], first_s[HH];
    for (int i = tid; i < HH; i += 256) {
        last_s[i]  = g_hA[b * HH + i];
        first_s[i] = g_enc_out[((size_t)b * TEE + 0) * HH + i];
    }
    __syncthreads();
    const int w = tid >> 5, lane = tid & 31;
    for (int t = w; t < TEE; t += 8) {
        const float* orow = g_enc_out + ((size_t)(b * TEE + t)) * HH;
        float af = 0.0f, ab = 0.0f;
        #pragma unroll 4
        for (int i = lane; i < HH; i += 32) {
            float v = orow[i];
            af += v * last_s[i];
            ab += v * first_s[i];
        }
        #pragma unroll
        for (int o = 16; o > 0; o >>= 1) {
            af += __shfl_xor_sync(0xffffffffu, af, o);
            ab += __shfl_xor_sync(0xffffffffu, ab, o);
        }
        if (lane == 0) { g_sfw[b * TEE + t] = af; g_sbw[b * TEE + t] = ab; }
    }
}

__device__ __forceinline__ float blk_reduce(float v, float* red, bool ismax) {
    #pragma unroll
    for (int o = 16; o > 0; o >>= 1) {
        float u = __shfl_xor_sync(0xffffffffu, v, o);
        v = ismax ? fmaxf(v, u) : (v + u);
    }
    int w = threadIdx.x >> 5;
    if ((threadIdx.x & 31) == 0) red[w] = v;
    __syncthreads();
    if (threadIdx.x == 0) {
        float a = red[0];
        for (int i = 1; i < 8; i++) a = ismax ? fmaxf(a, red[i]) : (a + red[i]);
        red[0] = a;
    }
    __syncthreads();
    float r = red[0];
    __syncthreads();
    return r;
}

// ---------------------------------------------------------------------------
// Masked dual softmax + semantic pooling + h_enc assembly (R1-proven).
// ---------------------------------------------------------------------------
__global__ __launch_bounds__(256) void softmax_semantic(const int* __restrict__ enc_len) {
    const int b = blockIdx.x, tid = threadIdx.x;
    const int len = enc_len[b];
    __shared__ float sa[TEE];
    __shared__ float red[8];

    // forward pass
    float v0 = (tid       < len) ? g_sfw[b * TEE + tid]       : -1e30f;
    float v1 = (tid + 256 < len) ? g_sfw[b * TEE + tid + 256] : -1e30f;
    float M = blk_reduce(fmaxf(v0, v1), red, true);
    float e0 = (tid       < len) ? expf(v0 - M) : 0.0f;
    float e1 = (tid + 256 < len) ? expf(v1 - M) : 0.0f;
    float S = blk_reduce(e0 + e1, red, false);
    float inv = 0.5f / S;
    sa[tid] = e0 * inv; sa[tid + 256] = e1 * inv;
    __syncthreads();

    // backward pass
    v0 = (tid       < len) ? g_sbw[b * TEE + tid]       : -1e30f;
    v1 = (tid + 256 < len) ? g_sbw[b * TEE + tid + 256] : -1e30f;
    M = blk_reduce(fmaxf(v0, v1), red, true);
    e0 = (tid       < len) ? expf(v0 - M) : 0.0f;
    e1 = (tid + 256 < len) ? expf(v1 - M) : 0.0f;
    S = blk_reduce(e0 + e1, red, false);
    inv = 0.5f / S;
    sa[tid] += e0 * inv; sa[tid + 256] += e1 * inv;
    __syncthreads();

    // semantic[b,d] = sum_t alpha[t] * out[b,t,d];  h_enc = [last, semantic]
    for (int d = tid; d < HH; d += 256) {
        float acc = 0.0f;
        #pragma unroll 4
        for (int t = 0; t < TEE; t++)
            acc += sa[t] * g_enc_out[((size_t)(b * TEE + t)) * HH + d];
        g_henc[b * 2 * HH + HH + d] = acc;
        g_henc[b * 2 * HH + d] = g_hA[b * HH + d];
    }
}

// ---------------------------------------------------------------------------
// Latent head (R1-proven): mu/sigma/z + tail outputs. 1 block per b.
// ---------------------------------------------------------------------------
__global__ __launch_bounds__(256) void latent_head(
    const float* __restrict__ W_mu, const float* __restrict__ b_mu,
    const float* __restrict__ W_ls, const float* __restrict__ b_ls,
    const float* __restrict__ noise, const int* __restrict__ dec_len,
    float* __restrict__ outbuf)
{
    const int b = blockIdx.x, tid = threadIdx.x;
    __shared__ float he[2 * HH];
    __shared__ float muv[LL], lsv[LL];
    for (int i = tid; i < 2 * HH; i += 256) he[i] = g_henc[b * 2 * HH + i];
    __syncthreads();

    const int w = tid >> 5, lane = tid & 31;
    for (int o = w; o < 2 * LL; o += 8) {
        const float* Wr; float bia; int j;
        if (o < LL) { j = o;      Wr = W_mu + (size_t)j * (2 * HH); bia = b_mu[j]; }
        else        { j = o - LL; Wr = W_ls + (size_t)j * (2 * HH); bia = b_ls[j]; }
        float acc = 0.0f;
        #pragma unroll 4
        for (int k = lane; k < 2 * HH; k += 32) acc += Wr[k] * he[k];
        #pragma unroll
        for (int s = 16; s > 0; s >>= 1) acc += __shfl_xor_sync(0xffffffffu, acc, s);
        if (lane == 0) { if (o < LL) muv[j] = acc + bia; else lsv[j] = acc + bia; }
    }
    __syncthreads();

    if (tid < LL) {
        float mu = muv[tid];
        float sg = expf(lsv[tid]);
        float zz = mu + sg * noise[b * LL + tid];
        g_z[b * LL + tid] = zz;
        outbuf[OFF_MU + b * LL + tid] = mu;
        outbuf[OFF_SG + b * LL + tid] = sg;
    }
    if (b == 0 && tid == 0) {
        int m = 0;
        for (int i = 0; i < BB; i++) m = max(m, dec_len[i]);
        outbuf[OFF_ML] = (float)m;
    }
}

// ---------------------------------------------------------------------------
// Launch
// ---------------------------------------------------------------------------
extern "C" void kernel_launch(void* const* d_in, const int* in_sizes, int n_in,
                              void* d_out, int out_size) {
    const float* emb     = (const float*)d_in[0];
    const float* enc_Wih = (const float*)d_in[1];
    const float* enc_Whh = (const float*)d_in[2];
    const float* enc_bih = (const float*)d_in[3];
    const float* enc_bhh = (const float*)d_in[4];
    const float* dec_Wih = (const float*)d_in[5];
    const float* dec_Whh = (const float*)d_in[6];
    const float* dec_bih = (const float*)d_in[7];
    const float* dec_bhh = (const float*)d_in[8];
    const float* W_mu    = (const float*)d_in[9];
    const float* b_mu    = (const float*)d_in[10];
    const float* W_ls    = (const float*)d_in[11];
    const float* b_ls    = (const float*)d_in[12];
    const float* W_fc    = (const float*)d_in[13];
    const float* b_fc    = (const float*)d_in[14];
    const float* noise   = (const float*)d_in[15];
    const int*   enc_ids = (const int*)d_in[16];
    const int*   enc_len = (const int*)d_in[17];
    const int*   dec_ids = (const int*)d_in[18];
    const int*   dec_len = (const int*)d_in[19];
    float* outbuf = (float*)d_out;

    float *p_gx_enc, *p_enc_out, *p_gx_dec, *p_dec_out, *p_hA, *p_hB, *p_z;
    cudaGetSymbolAddress((void**)&p_gx_enc, g_gx_enc);
    cudaGetSymbolAddress((void**)&p_enc_out, g_enc_out);
    cudaGetSymbolAddress((void**)&p_gx_dec, g_gx_dec);
    cudaGetSymbolAddress((void**)&p_dec_out, g_dec_out);
    cudaGetSymbolAddress((void**)&p_hA, g_hA);
    cudaGetSymbolAddress((void**)&p_hB, g_hB);
    cudaGetSymbolAddress((void**)&p_z, g_z);

    // 1) gx_enc = emb[enc_ids] @ enc_Wih^T + bih   [8192 x 1536, K=512]
    gemm_nt128<512><<<dim3(1536 / 128, (BB * TEE) / 128), 256>>>(
        p_gx_enc, nullptr, enc_ids, emb, enc_Wih, enc_bih, 3 * HH, nullptr, 1);

    // 2-3) padding no-ops (place gru_enc at my launch #4 = profiled slot)
    noop_a<<<1, 32>>>();
    noop_b<<<1, 32>>>();

    // 4) encoder GRU (persistent, 512 steps)  <-- profiled launch
    gru_persist<HH, 4><<<HH / 4, 256>>>(
        p_gx_enc, enc_Whh, enc_bhh, enc_len, nullptr, p_hA, p_hB, p_enc_out, TEE);

    // 5-7) attention + latent path (R1 versions)
    attn_scores<<<BB, 256>>>();
    softmax_semantic<<<BB, 256>>>(enc_len);
    latent_head<<<BB, 256>>>(W_mu, b_mu, W_ls, b_ls, noise, dec_len, outbuf);

    // 8) gx_dec = emb[dec_ids] @ dec_Wih^T + bih   [4096 x 768, K=512]
    gemm_nt128<512><<<dim3((3 * LL) / 128, (BB * TDD) / 128), 256>>>(
        p_gx_dec, nullptr, dec_ids, emb, dec_Wih, dec_bih, 3 * LL, nullptr, 1);

    // 9) decoder GRU (persistent, 256 steps), h0 = z
    gru_persist<LL, 2><<<LL / 2, 256>>>(
        p_gx_dec, dec_Whh, dec_bhh, dec_len, p_z, p_hA, p_hB, p_dec_out, TDD);

    // 10) logits = dec_out @ W_fc^T + b_fc  [4096 x 32000, K=256], zero-row skip
    gemm_nt128<256><<<dim3(VV / 128, (BB * TDD) / 128), 256>>>(
        outbuf, p_dec_out, nullptr, nullptr, W_fc, b_fc, VV, dec_len, TDD);
}